// round 16
// baseline (speedup 1.0000x reference)
#include <cuda_runtime.h>
#include <cuda_bf16.h>
#include <cstdint>

#define VOCAB 100000
#define EMB   300
#define BSZ   2048
#define SEQL  200
#define HID   128
#define OUTD  20

#define EMB4  (EMB / 4)          // 75 float4 per row
#define SPB2  4                  // samples per MLP block -> grid 512
#define DCH   10                 // d-chunks of exactly 30 rows (10*30=300)
#define MLPT  320                // MLP block threads = 32 jg x 10 c

// rep scratch in MLP consumption layout: [B/4][EMB][4] floats.
__device__ float g_repT[(BSZ / SPB2) * EMB * SPB2];

// ---------------------------------------------------------------------------
// Kernel 1: embedding-bag mean.  Gather loop at the LTS cap — UNCHANGED.
// Serial launch (PDL regressed; gather must own the whole machine).
// ---------------------------------------------------------------------------
__global__ __launch_bounds__(256) void gather_kernel(
    const int*    __restrict__ x,        // [B, L]
    const int*    __restrict__ lengths,  // [B]
    const float4* __restrict__ emb4)     // [VOCAB, 75]
{
    const int gid = blockIdx.x * 256 + threadIdx.x;
    if (gid >= BSZ * EMB4) return;
    const int b = gid / EMB4;
    const int d = gid - b * EMB4;

    const int4* xb4 = (const int4*)(x + (size_t)b * SEQL);

    float4 a0 = make_float4(0.f, 0.f, 0.f, 0.f);
    float4 a1 = a0, a2 = a0, a3 = a0, a4 = a0, a5 = a0, a6 = a0, a7 = a0;

    #pragma unroll 1
    for (int it = 0; it < 25; ++it) {
        const int4 ia = __ldg(xb4 + it * 2 + 0);
        const int4 ib = __ldg(xb4 + it * 2 + 1);
        const float4 v0 = __ldg(emb4 + (size_t)ia.x * EMB4 + d);
        const float4 v1 = __ldg(emb4 + (size_t)ia.y * EMB4 + d);
        const float4 v2 = __ldg(emb4 + (size_t)ia.z * EMB4 + d);
        const float4 v3 = __ldg(emb4 + (size_t)ia.w * EMB4 + d);
        const float4 v4 = __ldg(emb4 + (size_t)ib.x * EMB4 + d);
        const float4 v5 = __ldg(emb4 + (size_t)ib.y * EMB4 + d);
        const float4 v6 = __ldg(emb4 + (size_t)ib.z * EMB4 + d);
        const float4 v7 = __ldg(emb4 + (size_t)ib.w * EMB4 + d);
        a0.x += v0.x; a0.y += v0.y; a0.z += v0.z; a0.w += v0.w;
        a1.x += v1.x; a1.y += v1.y; a1.z += v1.z; a1.w += v1.w;
        a2.x += v2.x; a2.y += v2.y; a2.z += v2.z; a2.w += v2.w;
        a3.x += v3.x; a3.y += v3.y; a3.z += v3.z; a3.w += v3.w;
        a4.x += v4.x; a4.y += v4.y; a4.z += v4.z; a4.w += v4.w;
        a5.x += v5.x; a5.y += v5.y; a5.z += v5.z; a5.w += v5.w;
        a6.x += v6.x; a6.y += v6.y; a6.z += v6.z; a6.w += v6.w;
        a7.x += v7.x; a7.y += v7.y; a7.z += v7.z; a7.w += v7.w;
    }

    const float inv = 1.0f / (float)__ldg(lengths + b);
    const float rx = (a0.x + a1.x + a2.x + a3.x + a4.x + a5.x + a6.x + a7.x) * inv;
    const float ry = (a0.y + a1.y + a2.y + a3.y + a4.y + a5.y + a6.y + a7.y) * inv;
    const float rz = (a0.z + a1.z + a2.z + a3.z + a4.z + a5.z + a6.z + a7.z) * inv;
    const float rw = (a0.w + a1.w + a2.w + a3.w + a4.w + a5.w + a6.w + a7.w) * inv;

    // transposed store: g_repT[bg][4d+k][s]
    const int bg = b >> 2, si = b & 3;
    float* dst = g_repT + ((size_t)bg * EMB + 4 * d) * SPB2 + si;
    dst[0]  = rx;
    dst[4]  = ry;
    dst[8]  = rz;
    dst[12] = rw;
}

// ---------------------------------------------------------------------------
// Kernel 2: logits = relu(rep @ W1 + b1) @ W2 + b2.
// R14 GEMM1 (packed f32x2) + vectorized combine + b1 staged in smem.
// ---------------------------------------------------------------------------
__global__ __launch_bounds__(MLPT) void mlp_kernel(
    const float* __restrict__ W1,   // [EMB, HID]
    const float* __restrict__ b1,   // [HID]
    const float* __restrict__ W2,   // [HID, OUTD]
    const float* __restrict__ b2,   // [OUTD]
    float*       __restrict__ out)  // [B, OUTD]
{
    __shared__ __align__(16) float repT[EMB][SPB2];         // 4.8 KB
    __shared__ __align__(16) float hpart[DCH][SPB2][HID];   // 20 KB
    __shared__ __align__(16) float hbuf[SPB2][HID];         // 2 KB
    __shared__ float W2s[HID * OUTD];                       // 10 KB
    __shared__ __align__(16) float b1s[HID];                // 0.5 KB
    __shared__ float g2part[4][SPB2][OUTD];                 // 1.25 KB

    const int tid = threadIdx.x;
    const int bg  = blockIdx.x;
    const int b0  = bg * SPB2;

    // ---- stage W2 + b1 into smem (ordered by post-GEMM1 barriers) ----------
    #pragma unroll
    for (int i = 0; i < (HID * OUTD + MLPT - 1) / MLPT; ++i) {
        const int idx = tid + i * MLPT;
        if (idx < HID * OUTD) W2s[idx] = __ldg(&W2[idx]);
    }
    if (tid < HID) b1s[tid] = __ldg(&b1[tid]);

    // ---- stage rep tile: identity copy, coalesced, conflict-free -----------
    if (tid < SPB2 * EMB4) {   // 300 threads x float4 = [EMB][SPB2]
        const float4 v = *((const float4*)(g_repT + (size_t)bg * EMB * SPB2) + tid);
        *((float4*)&repT[0][0] + tid) = v;
    }

    // ---- GEMM1 setup + W1 prefetch BEFORE the barrier -----------------------
    const int jg = tid & 31;               // cols 4jg..4jg+3
    const int c  = tid >> 5;               // d-chunk 0..9
    const int d0 = c * 30;
    const float4* W14 = (const float4*)W1; // [EMB][32] float4
    float4 w = __ldg(&W14[(size_t)d0 * 32 + jg]);

    __syncthreads();

    // ---- GEMM1: packed f32x2 FMA -------------------------------------------
    {
        uint64_t acc01[4] = {0ull, 0ull, 0ull, 0ull};
        uint64_t acc23[4] = {0ull, 0ull, 0ull, 0ull};

        const uint32_t rep_base =
            (uint32_t)__cvta_generic_to_shared(&repT[0][0]);

        uint64_t r01, r23;
        asm volatile("ld.shared.v2.u64 {%0, %1}, [%2];"
                     : "=l"(r01), "=l"(r23)
                     : "r"(rep_base + (uint32_t)(d0 * 16)));

        #pragma unroll
        for (int k = 0; k < 30; ++k) {
            const float4   wc   = w;
            const uint64_t rc01 = r01, rc23 = r23;
            const int dn = d0 + ((k + 1) % 30);      // compile-time; wraps to d0
            w = __ldg(&W14[(size_t)dn * 32 + jg]);
            asm volatile("ld.shared.v2.u64 {%0, %1}, [%2];"
                         : "=l"(r01), "=l"(r23)
                         : "r"(rep_base + (uint32_t)(dn * 16)));

            uint64_t wj;
            asm volatile("mov.b64 %0, {%1, %1};" : "=l"(wj) : "f"(wc.x));
            asm volatile("fma.rn.f32x2 %0, %1, %2, %0;" : "+l"(acc01[0]) : "l"(rc01), "l"(wj));
            asm volatile("fma.rn.f32x2 %0, %1, %2, %0;" : "+l"(acc23[0]) : "l"(rc23), "l"(wj));
            asm volatile("mov.b64 %0, {%1, %1};" : "=l"(wj) : "f"(wc.y));
            asm volatile("fma.rn.f32x2 %0, %1, %2, %0;" : "+l"(acc01[1]) : "l"(rc01), "l"(wj));
            asm volatile("fma.rn.f32x2 %0, %1, %2, %0;" : "+l"(acc23[1]) : "l"(rc23), "l"(wj));
            asm volatile("mov.b64 %0, {%1, %1};" : "=l"(wj) : "f"(wc.z));
            asm volatile("fma.rn.f32x2 %0, %1, %2, %0;" : "+l"(acc01[2]) : "l"(rc01), "l"(wj));
            asm volatile("fma.rn.f32x2 %0, %1, %2, %0;" : "+l"(acc23[2]) : "l"(rc23), "l"(wj));
            asm volatile("mov.b64 %0, {%1, %1};" : "=l"(wj) : "f"(wc.w));
            asm volatile("fma.rn.f32x2 %0, %1, %2, %0;" : "+l"(acc01[3]) : "l"(rc01), "l"(wj));
            asm volatile("fma.rn.f32x2 %0, %1, %2, %0;" : "+l"(acc23[3]) : "l"(rc23), "l"(wj));
        }

        float s0v[4], s1v[4], s2v[4], s3v[4];
        #pragma unroll
        for (int j = 0; j < 4; ++j) {
            asm("mov.b64 {%0, %1}, %2;" : "=f"(s0v[j]), "=f"(s1v[j]) : "l"(acc01[j]));
            asm("mov.b64 {%0, %1}, %2;" : "=f"(s2v[j]), "=f"(s3v[j]) : "l"(acc23[j]));
        }
        *(float4*)&hpart[c][0][4 * jg] = make_float4(s0v[0], s0v[1], s0v[2], s0v[3]);
        *(float4*)&hpart[c][1][4 * jg] = make_float4(s1v[0], s1v[1], s1v[2], s1v[3]);
        *(float4*)&hpart[c][2][4 * jg] = make_float4(s2v[0], s2v[1], s2v[2], s2v[3]);
        *(float4*)&hpart[c][3][4 * jg] = make_float4(s3v[0], s3v[1], s3v[2], s3v[3]);
    }
    __syncthreads();

    // ---- combine partials + bias + relu (vectorized: 128 threads x float4) --
    if (tid < SPB2 * HID / 4) {            // 128 threads
        const int s  = tid >> 5;           // 0..3
        const int j4 = tid & 31;           // float4 column group
        float4 v = *(const float4*)&b1s[4 * j4];
        #pragma unroll
        for (int cc = 0; cc < DCH; ++cc) {
            const float4 p = *(const float4*)&hpart[cc][s][4 * j4];
            v.x += p.x; v.y += p.y; v.z += p.z; v.w += p.w;
        }
        v.x = v.x > 0.f ? v.x : 0.f;
        v.y = v.y > 0.f ? v.y : 0.f;
        v.z = v.z > 0.f ? v.z : 0.f;
        v.w = v.w > 0.f ? v.w : 0.f;
        *(float4*)&hbuf[s][4 * j4] = v;
    }
    __syncthreads();

    // ---- GEMM2, k-split over all 320 threads --------------------------------
    {
        const int p  = tid % 80;
        const int kc = tid / 80;               // 0..3
        const int s  = p / OUTD;
        const int o  = p - s * OUTD;
        const int k0 = kc * 32;

        float a0 = 0.f, a1 = 0.f, a2 = 0.f, a3 = 0.f;
        #pragma unroll
        for (int k = 0; k < 32; k += 4) {
            a0 += hbuf[s][k0 + k + 0] * W2s[(k0 + k + 0) * OUTD + o];
            a1 += hbuf[s][k0 + k + 1] * W2s[(k0 + k + 1) * OUTD + o];
            a2 += hbuf[s][k0 + k + 2] * W2s[(k0 + k + 2) * OUTD + o];
            a3 += hbuf[s][k0 + k + 3] * W2s[(k0 + k + 3) * OUTD + o];
        }
        g2part[kc][s][o] = (a0 + a1) + (a2 + a3);
    }
    __syncthreads();

    if (tid < SPB2 * OUTD) {
        const int s = tid / OUTD;
        const int o = tid - s * OUTD;
        out[(size_t)(b0 + s) * OUTD + o] = __ldg(&b2[o])
            + (g2part[0][s][o] + g2part[1][s][o])
            + (g2part[2][s][o] + g2part[3][s][o]);
    }
}

extern "C" void kernel_launch(void* const* d_in, const int* in_sizes, int n_in,
                              void* d_out, int out_size)
{
    const int*    x       = (const int*)    d_in[0];
    const int*    lengths = (const int*)    d_in[1];
    const float4* emb4    = (const float4*) d_in[2];
    const float*  W1      = (const float*)  d_in[3];
    const float*  b1      = (const float*)  d_in[4];
    const float*  W2      = (const float*)  d_in[5];
    const float*  b2      = (const float*)  d_in[6];
    float*        out     = (float*)        d_out;

    const int gather_items = BSZ * EMB4;                    // 153600
    gather_kernel<<<(gather_items + 255) / 256, 256>>>(x, lengths, emb4);
    mlp_kernel<<<BSZ / SPB2, MLPT>>>(W1, b1, W2, b2, out);  // 512 blocks
}

// round 17
// speedup vs baseline: 1.1245x; 1.1245x over previous
#include <cuda_runtime.h>
#include <cuda_bf16.h>
#include <cstdint>

#define VOCAB 100000
#define EMB   300
#define BSZ   2048
#define SEQL  200
#define HID   128
#define OUTD  20

#define EMB4  (EMB / 4)          // 75 float4 per row
#define SPB2  4                  // samples per MLP block -> grid 512
#define DCH   10                 // d-chunks of exactly 30 rows (10*30=300)
#define MLPT  320                // MLP block threads = 32 jg x 10 c

// rep scratch in MLP consumption layout: [B/4][EMB][4] floats.
__device__ float g_repT[(BSZ / SPB2) * EMB * SPB2];

// ---------------------------------------------------------------------------
// Kernel 1: embedding-bag mean.  Gather loop at the LTS cap — UNCHANGED.
// ---------------------------------------------------------------------------
__global__ __launch_bounds__(256) void gather_kernel(
    const int*    __restrict__ x,        // [B, L]
    const int*    __restrict__ lengths,  // [B]
    const float4* __restrict__ emb4)     // [VOCAB, 75]
{
    const int gid = blockIdx.x * 256 + threadIdx.x;
    if (gid >= BSZ * EMB4) return;
    const int b = gid / EMB4;
    const int d = gid - b * EMB4;

    const int4* xb4 = (const int4*)(x + (size_t)b * SEQL);

    float4 a0 = make_float4(0.f, 0.f, 0.f, 0.f);
    float4 a1 = a0, a2 = a0, a3 = a0, a4 = a0, a5 = a0, a6 = a0, a7 = a0;

    #pragma unroll 1
    for (int it = 0; it < 25; ++it) {
        const int4 ia = __ldg(xb4 + it * 2 + 0);
        const int4 ib = __ldg(xb4 + it * 2 + 1);
        const float4 v0 = __ldg(emb4 + (size_t)ia.x * EMB4 + d);
        const float4 v1 = __ldg(emb4 + (size_t)ia.y * EMB4 + d);
        const float4 v2 = __ldg(emb4 + (size_t)ia.z * EMB4 + d);
        const float4 v3 = __ldg(emb4 + (size_t)ia.w * EMB4 + d);
        const float4 v4 = __ldg(emb4 + (size_t)ib.x * EMB4 + d);
        const float4 v5 = __ldg(emb4 + (size_t)ib.y * EMB4 + d);
        const float4 v6 = __ldg(emb4 + (size_t)ib.z * EMB4 + d);
        const float4 v7 = __ldg(emb4 + (size_t)ib.w * EMB4 + d);
        a0.x += v0.x; a0.y += v0.y; a0.z += v0.z; a0.w += v0.w;
        a1.x += v1.x; a1.y += v1.y; a1.z += v1.z; a1.w += v1.w;
        a2.x += v2.x; a2.y += v2.y; a2.z += v2.z; a2.w += v2.w;
        a3.x += v3.x; a3.y += v3.y; a3.z += v3.z; a3.w += v3.w;
        a4.x += v4.x; a4.y += v4.y; a4.z += v4.z; a4.w += v4.w;
        a5.x += v5.x; a5.y += v5.y; a5.z += v5.z; a5.w += v5.w;
        a6.x += v6.x; a6.y += v6.y; a6.z += v6.z; a6.w += v6.w;
        a7.x += v7.x; a7.y += v7.y; a7.z += v7.z; a7.w += v7.w;
    }

    const float inv = 1.0f / (float)__ldg(lengths + b);
    const float rx = (a0.x + a1.x + a2.x + a3.x + a4.x + a5.x + a6.x + a7.x) * inv;
    const float ry = (a0.y + a1.y + a2.y + a3.y + a4.y + a5.y + a6.y + a7.y) * inv;
    const float rz = (a0.z + a1.z + a2.z + a3.z + a4.z + a5.z + a6.z + a7.z) * inv;
    const float rw = (a0.w + a1.w + a2.w + a3.w + a4.w + a5.w + a6.w + a7.w) * inv;

    // transposed store: g_repT[bg][4d+k][s]
    const int bg = b >> 2, si = b & 3;
    float* dst = g_repT + ((size_t)bg * EMB + 4 * d) * SPB2 + si;
    dst[0]  = rx;
    dst[4]  = ry;
    dst[8]  = rz;
    dst[12] = rw;
}

// ---------------------------------------------------------------------------
// Kernel 2: logits = relu(rep @ W1 + b1) @ W2 + b2.
// R13 structure; GEMM1 inner loop uses packed fma.rn.f32x2 (R14 — proven
// 11.0us).  Byte-identical resubmission of the 51.7us configuration.
// ---------------------------------------------------------------------------
__global__ __launch_bounds__(MLPT) void mlp_kernel(
    const float* __restrict__ W1,   // [EMB, HID]
    const float* __restrict__ b1,   // [HID]
    const float* __restrict__ W2,   // [HID, OUTD]
    const float* __restrict__ b2,   // [OUTD]
    float*       __restrict__ out)  // [B, OUTD]
{
    __shared__ __align__(16) float repT[EMB][SPB2];         // 4.8 KB
    __shared__ __align__(16) float hpart[DCH][SPB2][HID];   // 20 KB
    __shared__ float hbuf[SPB2][HID];                       // 2 KB
    __shared__ float W2s[HID * OUTD];                       // 10 KB
    __shared__ float g2part[4][SPB2][OUTD];                 // 1.25 KB

    const int tid = threadIdx.x;
    const int bg  = blockIdx.x;
    const int b0  = bg * SPB2;

    // ---- stage W2 into smem (ordered by the post-GEMM1 barriers) -----------
    #pragma unroll
    for (int i = 0; i < (HID * OUTD + MLPT - 1) / MLPT; ++i) {
        const int idx = tid + i * MLPT;
        if (idx < HID * OUTD) W2s[idx] = __ldg(&W2[idx]);
    }

    // ---- stage rep tile: identity copy, coalesced, conflict-free -----------
    if (tid < SPB2 * EMB4) {   // 300 threads x float4 = [EMB][SPB2]
        const float4 v = *((const float4*)(g_repT + (size_t)bg * EMB * SPB2) + tid);
        *((float4*)&repT[0][0] + tid) = v;
    }

    // ---- GEMM1 setup + W1 prefetch BEFORE the barrier -----------------------
    const int jg = tid & 31;               // cols 4jg..4jg+3
    const int c  = tid >> 5;               // d-chunk 0..9
    const int d0 = c * 30;
    const float4* W14 = (const float4*)W1; // [EMB][32] float4
    float4 w = __ldg(&W14[(size_t)d0 * 32 + jg]);

    __syncthreads();

    // ---- GEMM1: packed f32x2 FMA -------------------------------------------
    {
        // acc01[j] = (h[s0][4jg+j], h[s1][4jg+j]); acc23[j] likewise for s2,s3
        uint64_t acc01[4] = {0ull, 0ull, 0ull, 0ull};
        uint64_t acc23[4] = {0ull, 0ull, 0ull, 0ull};

        const uint32_t rep_base =
            (uint32_t)__cvta_generic_to_shared(&repT[0][0]);

        uint64_t r01, r23;
        asm volatile("ld.shared.v2.u64 {%0, %1}, [%2];"
                     : "=l"(r01), "=l"(r23)
                     : "r"(rep_base + (uint32_t)(d0 * 16)));

        #pragma unroll
        for (int k = 0; k < 30; ++k) {
            const float4   wc  = w;
            const uint64_t rc01 = r01, rc23 = r23;
            const int dn = d0 + ((k + 1) % 30);      // compile-time; wraps to d0
            w = __ldg(&W14[(size_t)dn * 32 + jg]);   // prefetch next W1 row
            asm volatile("ld.shared.v2.u64 {%0, %1}, [%2];"
                         : "=l"(r01), "=l"(r23)
                         : "r"(rep_base + (uint32_t)(dn * 16)));

            uint64_t wj;
            // j = 0
            asm volatile("mov.b64 %0, {%1, %1};" : "=l"(wj) : "f"(wc.x));
            asm volatile("fma.rn.f32x2 %0, %1, %2, %0;" : "+l"(acc01[0]) : "l"(rc01), "l"(wj));
            asm volatile("fma.rn.f32x2 %0, %1, %2, %0;" : "+l"(acc23[0]) : "l"(rc23), "l"(wj));
            // j = 1
            asm volatile("mov.b64 %0, {%1, %1};" : "=l"(wj) : "f"(wc.y));
            asm volatile("fma.rn.f32x2 %0, %1, %2, %0;" : "+l"(acc01[1]) : "l"(rc01), "l"(wj));
            asm volatile("fma.rn.f32x2 %0, %1, %2, %0;" : "+l"(acc23[1]) : "l"(rc23), "l"(wj));
            // j = 2
            asm volatile("mov.b64 %0, {%1, %1};" : "=l"(wj) : "f"(wc.z));
            asm volatile("fma.rn.f32x2 %0, %1, %2, %0;" : "+l"(acc01[2]) : "l"(rc01), "l"(wj));
            asm volatile("fma.rn.f32x2 %0, %1, %2, %0;" : "+l"(acc23[2]) : "l"(rc23), "l"(wj));
            // j = 3
            asm volatile("mov.b64 %0, {%1, %1};" : "=l"(wj) : "f"(wc.w));
            asm volatile("fma.rn.f32x2 %0, %1, %2, %0;" : "+l"(acc01[3]) : "l"(rc01), "l"(wj));
            asm volatile("fma.rn.f32x2 %0, %1, %2, %0;" : "+l"(acc23[3]) : "l"(rc23), "l"(wj));
        }

        // unpack: acc01[j] = (s0, s1), acc23[j] = (s2, s3) for col 4jg+j
        float s0v[4], s1v[4], s2v[4], s3v[4];
        #pragma unroll
        for (int j = 0; j < 4; ++j) {
            asm("mov.b64 {%0, %1}, %2;" : "=f"(s0v[j]), "=f"(s1v[j]) : "l"(acc01[j]));
            asm("mov.b64 {%0, %1}, %2;" : "=f"(s2v[j]), "=f"(s3v[j]) : "l"(acc23[j]));
        }
        *(float4*)&hpart[c][0][4 * jg] = make_float4(s0v[0], s0v[1], s0v[2], s0v[3]);
        *(float4*)&hpart[c][1][4 * jg] = make_float4(s1v[0], s1v[1], s1v[2], s1v[3]);
        *(float4*)&hpart[c][2][4 * jg] = make_float4(s2v[0], s2v[1], s2v[2], s2v[3]);
        *(float4*)&hpart[c][3][4 * jg] = make_float4(s3v[0], s3v[1], s3v[2], s3v[3]);
    }
    __syncthreads();

    // ---- combine partials + bias + relu ------------------------------------
    for (int i = tid; i < SPB2 * HID; i += MLPT) {
        const int s = i >> 7;
        const int j = i & (HID - 1);
        float v = __ldg(&b1[j]);
        #pragma unroll
        for (int cc = 0; cc < DCH; ++cc) v += hpart[cc][s][j];
        hbuf[s][j] = v > 0.0f ? v : 0.0f;
    }
    __syncthreads();

    // ---- GEMM2, k-split over all 320 threads --------------------------------
    {
        const int p  = tid % 80;
        const int kc = tid / 80;               // 0..3
        const int s  = p / OUTD;
        const int o  = p - s * OUTD;
        const int k0 = kc * 32;

        float a0 = 0.f, a1 = 0.f, a2 = 0.f, a3 = 0.f;
        #pragma unroll
        for (int k = 0; k < 32; k += 4) {
            a0 += hbuf[s][k0 + k + 0] * W2s[(k0 + k + 0) * OUTD + o];
            a1 += hbuf[s][k0 + k + 1] * W2s[(k0 + k + 1) * OUTD + o];
            a2 += hbuf[s][k0 + k + 2] * W2s[(k0 + k + 2) * OUTD + o];
            a3 += hbuf[s][k0 + k + 3] * W2s[(k0 + k + 3) * OUTD + o];
        }
        g2part[kc][s][o] = (a0 + a1) + (a2 + a3);
    }
    __syncthreads();

    if (tid < SPB2 * OUTD) {
        const int s = tid / OUTD;
        const int o = tid - s * OUTD;
        out[(size_t)(b0 + s) * OUTD + o] = __ldg(&b2[o])
            + (g2part[0][s][o] + g2part[1][s][o])
            + (g2part[2][s][o] + g2part[3][s][o]);
    }
}

extern "C" void kernel_launch(void* const* d_in, const int* in_sizes, int n_in,
                              void* d_out, int out_size)
{
    const int*    x       = (const int*)    d_in[0];
    const int*    lengths = (const int*)    d_in[1];
    const float4* emb4    = (const float4*) d_in[2];
    const float*  W1      = (const float*)  d_in[3];
    const float*  b1      = (const float*)  d_in[4];
    const float*  W2      = (const float*)  d_in[5];
    const float*  b2      = (const float*)  d_in[6];
    float*        out     = (float*)        d_out;

    const int gather_items = BSZ * EMB4;                    // 153600
    gather_kernel<<<(gather_items + 255) / 256, 256>>>(x, lengths, emb4);
    mlp_kernel<<<BSZ / SPB2, MLPT>>>(W1, b1, W2, b2, out);  // 512 blocks
}